// round 2
// baseline (speedup 1.0000x reference)
#include <cuda_runtime.h>
#include <cuda_bf16.h>

// ---------------------------------------------------------------------------
// GCN_21260088115434: 3-layer GCN + dot-product link decode
//   deg[v] = indeg(v)+1 ; dinv = rsqrt(deg)
//   layer: g = dinv ⊙ (h @ W); acc = g (self-loop) + scatter_add g[src]->acc[dst]
//          h' = act(dinv ⊙ acc + b)
//   out[p] = dot(z[a_p], z[b_p])
// NOTE: edge indices are int32 (JAX x64 disabled downcasts int64 -> int32).
// ---------------------------------------------------------------------------

#define MAX_N 100000
#define D_HID 128

// scratch (device globals: no allocation allowed)
__device__ float g_dinv[MAX_N];
__device__ float g_bufG[(size_t)MAX_N * D_HID];   // GEMM output (scaled by dinv[row])
__device__ float g_bufA[(size_t)MAX_N * D_HID];   // aggregation accumulator
__device__ float g_bufH[(size_t)MAX_N * D_HID];   // layer activation

// ---------------------------------------------------------------------------
__global__ void deg_init_kernel(float* deg, int n) {
    int i = blockIdx.x * blockDim.x + threadIdx.x;
    if (i < n) deg[i] = 1.0f;   // self loop
}

__global__ void deg_count_kernel(const int* __restrict__ dst, float* deg, int e) {
    int i = blockIdx.x * blockDim.x + threadIdx.x;
    if (i < e) atomicAdd(&deg[dst[i]], 1.0f);
}

__global__ void deg_rsqrt_kernel(float* deg, int n) {
    int i = blockIdx.x * blockDim.x + threadIdx.x;
    if (i < n) deg[i] = rsqrtf(deg[i]);
}

// ---------------------------------------------------------------------------
// Register-tiled fp32 GEMM: out = dinv[row] * (A[N,128] @ W[128,BN])
// Dual store: writes result to BOTH outG (gather source) and outAcc
// (accumulator init = self-loop contribution).
// BM=128, BK=32, 256 threads, each thread computes 8 x (BN/16) outputs.
// ---------------------------------------------------------------------------
template <int BN>
__global__ __launch_bounds__(256)
void gemm_scale_kernel(const float* __restrict__ A, const float* __restrict__ W,
                       const float* __restrict__ dinv,
                       float* __restrict__ outG, float* __restrict__ outAcc,
                       int nrows) {
    constexpr int BM = 128, BK = 32;
    constexpr int TM = 8, TN = BN / 16;

    __shared__ float As[BK][BM];   // transposed A tile
    __shared__ float Ws[BK][BN];

    const int tid = threadIdx.x;
    const int ty = tid >> 4;    // 0..15
    const int tx = tid & 15;    // 0..15
    const int row0 = blockIdx.x * BM;

    float acc[TM][TN];
#pragma unroll
    for (int i = 0; i < TM; i++)
#pragma unroll
        for (int j = 0; j < TN; j++) acc[i][j] = 0.0f;

    for (int kk = 0; kk < 128; kk += BK) {
        // load A tile: BM x BK = 1024 float4, 4 per thread (transposed store)
#pragma unroll
        for (int i = 0; i < 4; i++) {
            int f = tid + i * 256;          // 0..1023
            int r = f >> 3;                 // row in tile (8 float4 per row)
            int c4 = f & 7;
            int grow = row0 + r;
            float4 v = make_float4(0.f, 0.f, 0.f, 0.f);
            if (grow < nrows)
                v = *(const float4*)(A + (size_t)grow * 128 + kk + c4 * 4);
            As[c4 * 4 + 0][r] = v.x;
            As[c4 * 4 + 1][r] = v.y;
            As[c4 * 4 + 2][r] = v.z;
            As[c4 * 4 + 3][r] = v.w;
        }
        // load W tile: BK x BN floats = BK*BN/4 float4
        constexpr int WF4 = BK * BN / 4;
#pragma unroll
        for (int i = 0; i < WF4 / 256; i++) {
            int f = tid + i * 256;
            int r = f / (BN / 4);
            int c4 = f % (BN / 4);
            *(float4*)(&Ws[r][c4 * 4]) =
                *(const float4*)(W + (size_t)(kk + r) * BN + c4 * 4);
        }
        __syncthreads();

#pragma unroll
        for (int k = 0; k < BK; k++) {
            float ra[TM], rb[TN];
#pragma unroll
            for (int i = 0; i < TM; i++) ra[i] = As[k][ty * TM + i];
#pragma unroll
            for (int j = 0; j < TN; j++) rb[j] = Ws[k][tx * TN + j];
#pragma unroll
            for (int i = 0; i < TM; i++)
#pragma unroll
                for (int j = 0; j < TN; j++) acc[i][j] += ra[i] * rb[j];
        }
        __syncthreads();
    }

    // epilogue: scale by dinv[row], dual store
#pragma unroll
    for (int i = 0; i < TM; i++) {
        int grow = row0 + ty * TM + i;
        if (grow < nrows) {
            float dv = dinv[grow];
#pragma unroll
            for (int j = 0; j < TN; j += 4) {
                float4 v;
                v.x = acc[i][j + 0] * dv;
                v.y = acc[i][j + 1] * dv;
                v.z = acc[i][j + 2] * dv;
                v.w = acc[i][j + 3] * dv;
                size_t off = (size_t)grow * BN + tx * TN + j;
                *(float4*)(outG + off) = v;
                *(float4*)(outAcc + off) = v;
            }
        }
    }
}

// ---------------------------------------------------------------------------
// Edge scatter: acc[dst] += g[src]  (vector RED, DV float4s per row)
// DV threads per edge; per-edge contiguous gather + vector RED.
// ---------------------------------------------------------------------------
template <int DV>
__global__ void scatter_kernel(const float* __restrict__ g,
                               const int* __restrict__ src,
                               const int* __restrict__ dst,
                               float* __restrict__ acc, int e) {
    int t = blockIdx.x * blockDim.x + threadIdx.x;
    int edge = t / DV;
    int j = t % DV;
    if (edge >= e) return;
    int s = src[edge];
    int d = dst[edge];
    float4 v = ((const float4*)g)[(size_t)s * DV + j];
    float4* p = ((float4*)acc) + (size_t)d * DV + j;
    asm volatile("red.global.add.v4.f32 [%0], {%1, %2, %3, %4};"
                 :: "l"(p), "f"(v.x), "f"(v.y), "f"(v.z), "f"(v.w)
                 : "memory");
}

// ---------------------------------------------------------------------------
// finish: out = act(dinv[row] * acc + b)
// ---------------------------------------------------------------------------
template <bool RELU, int D>
__global__ void finish_kernel(const float* __restrict__ acc,
                              const float* __restrict__ dinv,
                              const float* __restrict__ bias,
                              float* __restrict__ out, int nrows) {
    constexpr int DV = D / 4;
    int t = blockIdx.x * blockDim.x + threadIdx.x;
    if (t >= nrows * DV) return;
    int row = t / DV;
    int c4 = t % DV;
    float dv = dinv[row];
    float4 v = ((const float4*)acc)[t];
    float4 b = ((const float4*)bias)[c4];
    v.x = v.x * dv + b.x;
    v.y = v.y * dv + b.y;
    v.z = v.z * dv + b.z;
    v.w = v.w * dv + b.w;
    if (RELU) {
        v.x = fmaxf(v.x, 0.f);
        v.y = fmaxf(v.y, 0.f);
        v.z = fmaxf(v.z, 0.f);
        v.w = fmaxf(v.w, 0.f);
    }
    ((float4*)out)[t] = v;
}

// ---------------------------------------------------------------------------
// decode: out[p] = dot(z[a_p], z[b_p]), D=64 → 16 threads (float4 each) + shfl
// ---------------------------------------------------------------------------
__global__ void decode_kernel(const float* __restrict__ z,
                              const int* __restrict__ ia,
                              const int* __restrict__ ib,
                              float* __restrict__ out, int npairs) {
    int t = blockIdx.x * blockDim.x + threadIdx.x;
    int p = t >> 4;
    int l = t & 15;
    if (p >= npairs) return;
    int a = ia[p];
    int b = ib[p];
    float4 va = ((const float4*)z)[(size_t)a * 16 + l];
    float4 vb = ((const float4*)z)[(size_t)b * 16 + l];
    float s = va.x * vb.x + va.y * vb.y + va.z * vb.z + va.w * vb.w;
#pragma unroll
    for (int off = 8; off > 0; off >>= 1)
        s += __shfl_down_sync(0xffffffffu, s, off, 16);
    if (l == 0) out[p] = s;
}

// ---------------------------------------------------------------------------
extern "C" void kernel_launch(void* const* d_in, const int* in_sizes, int n_in,
                              void* d_out, int out_size) {
    const float* x = (const float*)d_in[0];
    const int* ei = (const int*)d_in[1];        // int32! (JAX x64 disabled)
    const int* eli = (const int*)d_in[2];
    const float* W1 = (const float*)d_in[3];
    const float* b1 = (const float*)d_in[4];
    const float* W2 = (const float*)d_in[5];
    const float* b2 = (const float*)d_in[6];
    const float* W3 = (const float*)d_in[7];
    const float* b3 = (const float*)d_in[8];
    float* out = (float*)d_out;

    const int N = in_sizes[0] / 128;
    const int E = in_sizes[1] / 2;
    const int EL = in_sizes[2] / 2;

    const int* src = ei;
    const int* dst = ei + E;

    float* dinv; cudaGetSymbolAddress((void**)&dinv, g_dinv);
    float* bufG; cudaGetSymbolAddress((void**)&bufG, g_bufG);
    float* bufA; cudaGetSymbolAddress((void**)&bufA, g_bufA);
    float* bufH; cudaGetSymbolAddress((void**)&bufH, g_bufH);

    const int TB = 256;
    // degrees -> dinv
    deg_init_kernel<<<(N + TB - 1) / TB, TB>>>(dinv, N);
    deg_count_kernel<<<(E + TB - 1) / TB, TB>>>(dst, dinv, E);
    deg_rsqrt_kernel<<<(N + TB - 1) / TB, TB>>>(dinv, N);

    const int gemmGrid = (N + 127) / 128;

    // ---- layer 1: x -> bufH (relu) ----
    gemm_scale_kernel<128><<<gemmGrid, 256>>>(x, W1, dinv, bufG, bufA, N);
    scatter_kernel<32><<<(int)(((long long)E * 32 + TB - 1) / TB), TB>>>(bufG, src, dst, bufA, E);
    finish_kernel<true, 128><<<(N * 32 + TB - 1) / TB, TB>>>(bufA, dinv, b1, bufH, N);

    // ---- layer 2: bufH -> bufH (relu) ----
    gemm_scale_kernel<128><<<gemmGrid, 256>>>(bufH, W2, dinv, bufG, bufA, N);
    scatter_kernel<32><<<(int)(((long long)E * 32 + TB - 1) / TB), TB>>>(bufG, src, dst, bufA, E);
    finish_kernel<true, 128><<<(N * 32 + TB - 1) / TB, TB>>>(bufA, dinv, b2, bufH, N);

    // ---- layer 3 (D=64): bufH -> bufH (no relu) ----
    gemm_scale_kernel<64><<<gemmGrid, 256>>>(bufH, W3, dinv, bufG, bufA, N);
    scatter_kernel<16><<<(int)(((long long)E * 16 + TB - 1) / TB), TB>>>(bufG, src, dst, bufA, E);
    finish_kernel<false, 64><<<(N * 16 + TB - 1) / TB, TB>>>(bufA, dinv, b3, bufH, N);

    // ---- decode ----
    decode_kernel<<<(int)(((long long)EL * 16 + TB - 1) / TB), TB>>>(bufH, eli, eli + EL, out, EL);
}

// round 3
// speedup vs baseline: 1.6272x; 1.6272x over previous
#include <cuda_runtime.h>
#include <cuda_bf16.h>

// ---------------------------------------------------------------------------
// GCN_21260088115434: 3-layer GCN + dot-product link decode
//   dinv = rsqrt(1 + indeg)
//   layer: g = dinv ⊙ (h @ W)           (f32x2 packed GEMM)
//          h' = act(dinv ⊙ (g[v] + Σ_{(s→v)} g[s]) + b)   (CSR segment reduce)
//   out[p] = dot(z[a_p], z[b_p])
// Edge indices are int32 (JAX x64 disabled).
// ---------------------------------------------------------------------------

#define MAX_N 100000
#define MAX_E 1600000
#define D_HID 128

__device__ float g_dinv[MAX_N];
__device__ float g_bufG[(size_t)MAX_N * D_HID];   // GEMM output (dinv-scaled)
__device__ float g_bufH[(size_t)MAX_N * D_HID];   // layer activation
__device__ int   g_cnt[MAX_N];
__device__ int   g_cur[MAX_N];
__device__ int   g_rowptr[MAX_N + 1];
__device__ int   g_csr[MAX_E];

// ---------------------------------------------------------------------------
__global__ void zero2_kernel(int* a, int* b, int n) {
    int i = blockIdx.x * blockDim.x + threadIdx.x;
    if (i < n) { a[i] = 0; b[i] = 0; }
}

__global__ void count_kernel(const int* __restrict__ dst, int* cnt, int e) {
    int i = blockIdx.x * blockDim.x + threadIdx.x;
    if (i < e) atomicAdd(&cnt[dst[i]], 1);
}

__global__ void dinv_kernel(const int* __restrict__ cnt, float* dinv, int n) {
    int i = blockIdx.x * blockDim.x + threadIdx.x;
    if (i < n) dinv[i] = rsqrtf(1.0f + (float)cnt[i]);
}

// single-block exclusive scan of cnt[0..n) -> rowptr[0..n]
__global__ void scan_kernel(const int* __restrict__ cnt, int* __restrict__ rowptr, int n) {
    __shared__ int sums[1024];
    int tid = threadIdx.x;
    int chunk = (n + 1023) >> 10;
    int beg = tid * chunk;
    int end = min(beg + chunk, n);
    int s = 0;
    for (int i = beg; i < end; i++) s += cnt[i];
    sums[tid] = s;
    __syncthreads();
    int own = s;
    for (int d = 1; d < 1024; d <<= 1) {
        int v = (tid >= d) ? sums[tid - d] : 0;
        __syncthreads();
        sums[tid] += v;
        __syncthreads();
    }
    int off = sums[tid] - own;   // exclusive prefix
    for (int i = beg; i < end; i++) { rowptr[i] = off; off += cnt[i]; }
    if (tid == 1023) rowptr[n] = off;
}

__global__ void fill_kernel(const int* __restrict__ src, const int* __restrict__ dst,
                            const int* __restrict__ rowptr, int* cur,
                            int* __restrict__ csr, int e) {
    int i = blockIdx.x * blockDim.x + threadIdx.x;
    if (i < e) {
        int d = dst[i];
        int pos = rowptr[d] + atomicAdd(&cur[d], 1);
        csr[pos] = src[i];
    }
}

// ---------------------------------------------------------------------------
// GEMM: out = dinv[row] * (A[N,128] @ W[128,BN]) using packed fma.rn.f32x2.
// BM=128, BK=32, 256 threads. Thread (ty,tx) owns rows ty*8..+7 and column
// pairs {2*tx + 32*j, +1}  (pair-strided: conflict-free LDS.64 on Ws).
// ---------------------------------------------------------------------------
template <int BN>
__global__ __launch_bounds__(256)
void gemm_scale_kernel(const float* __restrict__ A, const float* __restrict__ W,
                       const float* __restrict__ dinv,
                       float* __restrict__ outG, int nrows) {
    constexpr int BM = 128, BK = 32;
    constexpr int TM = 8, TN = BN / 16, NP = TN / 2;

    __shared__ float As[BK][BM];   // transposed A tile
    __shared__ float Ws[BK][BN];

    const int tid = threadIdx.x;
    const int ty = tid >> 4;    // 0..15
    const int tx = tid & 15;    // 0..15
    const int row0 = blockIdx.x * BM;

    unsigned long long acc[TM][NP] = {};   // f32x2 pairs, zero-init

    for (int kk = 0; kk < 128; kk += BK) {
        // load A tile: BM x BK = 1024 float4, 4 per thread (transposed store)
#pragma unroll
        for (int i = 0; i < 4; i++) {
            int f = tid + i * 256;
            int r = f >> 3;
            int c4 = f & 7;
            int grow = row0 + r;
            float4 v = make_float4(0.f, 0.f, 0.f, 0.f);
            if (grow < nrows)
                v = *(const float4*)(A + (size_t)grow * 128 + kk + c4 * 4);
            As[c4 * 4 + 0][r] = v.x;
            As[c4 * 4 + 1][r] = v.y;
            As[c4 * 4 + 2][r] = v.z;
            As[c4 * 4 + 3][r] = v.w;
        }
        // load W tile
        constexpr int WF4 = BK * BN / 4;
#pragma unroll
        for (int i = 0; i < WF4 / 256; i++) {
            int f = tid + i * 256;
            int r = f / (BN / 4);
            int c4 = f % (BN / 4);
            *(float4*)(&Ws[r][c4 * 4]) =
                *(const float4*)(W + (size_t)(kk + r) * BN + c4 * 4);
        }
        __syncthreads();

#pragma unroll
        for (int k = 0; k < BK; k++) {
            unsigned long long ap[TM], bp[NP];
#pragma unroll
            for (int i = 0; i < TM; i++) {
                float a = As[k][ty * TM + i];
                float2 t = make_float2(a, a);
                ap[i] = *(unsigned long long*)&t;
            }
#pragma unroll
            for (int j = 0; j < NP; j++)
                bp[j] = *(const unsigned long long*)&Ws[k][2 * tx + 32 * j];
#pragma unroll
            for (int i = 0; i < TM; i++)
#pragma unroll
                for (int j = 0; j < NP; j++)
                    asm("fma.rn.f32x2 %0, %1, %2, %0;"
                        : "+l"(acc[i][j]) : "l"(ap[i]), "l"(bp[j]));
        }
        __syncthreads();
    }

    // epilogue: scale by dinv[row], float2 stores (coalesced: lanes stride 2)
#pragma unroll
    for (int i = 0; i < TM; i++) {
        int grow = row0 + ty * TM + i;
        if (grow < nrows) {
            float dv = dinv[grow];
#pragma unroll
            for (int j = 0; j < NP; j++) {
                float2 v = *(float2*)&acc[i][j];
                v.x *= dv;
                v.y *= dv;
                *(float2*)(outG + (size_t)grow * BN + 2 * tx + 32 * j) = v;
            }
        }
    }
}

// ---------------------------------------------------------------------------
// CSR aggregation + epilogue: out[v] = act(dinv[v]*(g[v] + Σ g[csr[j]]) + b)
// D/4 threads per node, each owns one float4 column slice.
// ---------------------------------------------------------------------------
template <int D, bool RELU>
__global__ void aggregate_kernel(const float* __restrict__ g,
                                 const int* __restrict__ rowptr,
                                 const int* __restrict__ csr,
                                 const float* __restrict__ dinv,
                                 const float* __restrict__ bias,
                                 float* __restrict__ out, int n) {
    constexpr int TPN = D / 4;
    int t = blockIdx.x * blockDim.x + threadIdx.x;
    int v = t / TPN;
    int l = t % TPN;
    if (v >= n) return;
    const float4* g4 = (const float4*)g;

    float4 acc = g4[(size_t)v * TPN + l];   // self-loop
    int beg = rowptr[v], end = rowptr[v + 1];
    int j = beg;
    for (; j + 2 <= end; j += 2) {          // unroll-2 for MLP
        int s0 = csr[j], s1 = csr[j + 1];
        float4 m0 = g4[(size_t)s0 * TPN + l];
        float4 m1 = g4[(size_t)s1 * TPN + l];
        acc.x += m0.x + m1.x;
        acc.y += m0.y + m1.y;
        acc.z += m0.z + m1.z;
        acc.w += m0.w + m1.w;
    }
    if (j < end) {
        float4 m = g4[(size_t)csr[j] * TPN + l];
        acc.x += m.x; acc.y += m.y; acc.z += m.z; acc.w += m.w;
    }

    float dv = dinv[v];
    float4 b = ((const float4*)bias)[l];
    acc.x = acc.x * dv + b.x;
    acc.y = acc.y * dv + b.y;
    acc.z = acc.z * dv + b.z;
    acc.w = acc.w * dv + b.w;
    if (RELU) {
        acc.x = fmaxf(acc.x, 0.f);
        acc.y = fmaxf(acc.y, 0.f);
        acc.z = fmaxf(acc.z, 0.f);
        acc.w = fmaxf(acc.w, 0.f);
    }
    ((float4*)out)[(size_t)v * TPN + l] = acc;
}

// ---------------------------------------------------------------------------
// decode: out[p] = dot(z[a_p], z[b_p]), D=64 → 16 threads (float4) + shfl
// ---------------------------------------------------------------------------
__global__ void decode_kernel(const float* __restrict__ z,
                              const int* __restrict__ ia,
                              const int* __restrict__ ib,
                              float* __restrict__ out, int npairs) {
    int t = blockIdx.x * blockDim.x + threadIdx.x;
    int p = t >> 4;
    int l = t & 15;
    if (p >= npairs) return;
    int a = ia[p];
    int b = ib[p];
    float4 va = ((const float4*)z)[(size_t)a * 16 + l];
    float4 vb = ((const float4*)z)[(size_t)b * 16 + l];
    float s = va.x * vb.x + va.y * vb.y + va.z * vb.z + va.w * vb.w;
#pragma unroll
    for (int off = 8; off > 0; off >>= 1)
        s += __shfl_down_sync(0xffffffffu, s, off, 16);
    if (l == 0) out[p] = s;
}

// ---------------------------------------------------------------------------
extern "C" void kernel_launch(void* const* d_in, const int* in_sizes, int n_in,
                              void* d_out, int out_size) {
    const float* x = (const float*)d_in[0];
    const int* ei = (const int*)d_in[1];        // int32
    const int* eli = (const int*)d_in[2];
    const float* W1 = (const float*)d_in[3];
    const float* b1 = (const float*)d_in[4];
    const float* W2 = (const float*)d_in[5];
    const float* b2 = (const float*)d_in[6];
    const float* W3 = (const float*)d_in[7];
    const float* b3 = (const float*)d_in[8];
    float* out = (float*)d_out;

    const int N = in_sizes[0] / 128;
    const int E = in_sizes[1] / 2;
    const int EL = in_sizes[2] / 2;

    const int* src = ei;
    const int* dst = ei + E;

    float* dinv;  cudaGetSymbolAddress((void**)&dinv, g_dinv);
    float* bufG;  cudaGetSymbolAddress((void**)&bufG, g_bufG);
    float* bufH;  cudaGetSymbolAddress((void**)&bufH, g_bufH);
    int* cnt;     cudaGetSymbolAddress((void**)&cnt, g_cnt);
    int* cur;     cudaGetSymbolAddress((void**)&cur, g_cur);
    int* rowptr;  cudaGetSymbolAddress((void**)&rowptr, g_rowptr);
    int* csr;     cudaGetSymbolAddress((void**)&csr, g_csr);

    const int TB = 256;

    // ---- CSR build (once; shared by all 3 layers) ----
    zero2_kernel<<<(N + TB - 1) / TB, TB>>>(cnt, cur, N);
    count_kernel<<<(E + TB - 1) / TB, TB>>>(dst, cnt, E);
    scan_kernel<<<1, 1024>>>(cnt, rowptr, N);
    dinv_kernel<<<(N + TB - 1) / TB, TB>>>(cnt, dinv, N);
    fill_kernel<<<(E + TB - 1) / TB, TB>>>(src, dst, rowptr, cur, csr, E);

    const int gemmGrid = (N + 127) / 128;
    const int agg128 = (N * 32 + TB - 1) / TB;
    const int agg64  = (N * 16 + TB - 1) / TB;

    // ---- layer 1: x -> bufH (relu) ----
    gemm_scale_kernel<128><<<gemmGrid, 256>>>(x, W1, dinv, bufG, N);
    aggregate_kernel<128, true><<<agg128, TB>>>(bufG, rowptr, csr, dinv, b1, bufH, N);

    // ---- layer 2: bufH -> bufH (relu) ----
    gemm_scale_kernel<128><<<gemmGrid, 256>>>(bufH, W2, dinv, bufG, N);
    aggregate_kernel<128, true><<<agg128, TB>>>(bufG, rowptr, csr, dinv, b2, bufH, N);

    // ---- layer 3 (D=64): bufH -> bufH (no relu) ----
    gemm_scale_kernel<64><<<gemmGrid, 256>>>(bufH, W3, dinv, bufG, N);
    aggregate_kernel<64, false><<<agg64, TB>>>(bufG, rowptr, csr, dinv, b3, bufH, N);

    // ---- decode ----
    decode_kernel<<<(int)(((long long)EL * 16 + TB - 1) / TB), TB>>>(bufH, eli, eli + EL, out, EL);
}